// round 1
// baseline (speedup 1.0000x reference)
#include <cuda_runtime.h>
#include <cuda_bf16.h>

// ---------------- Problem constants ----------------
#define NNODES 50000
#define NEDGES 800000
#define ETOT   (NEDGES + NNODES)   // + self loops
#define INCH   128

// ---------------- Device scratch (no allocs allowed) ----------------
__device__ float g_xl[NNODES * 128];
__device__ float g_xr[NNODES * 128];
__device__ float g_h[NNODES * 128];     // layer activation ping buffer
__device__ float g_agg[NNODES * 128];   // aggregation target
__device__ float g_ex[ETOT * 2];        // logits then exp(logits - max)
__device__ float g_amax[NNODES * 2];
__device__ float g_denom[NNODES * 2];
__device__ int   g_src[ETOT];
__device__ int   g_dst[ETOT];
__device__ int   g_is64;

// ---------------- Helpers ----------------
__device__ __forceinline__ void atomicMaxF(float* addr, float val) {
    int* ia = (int*)addr;
    int old = __float_as_int(*addr);
    while (__int_as_float(old) < val) {
        int prev = atomicCAS(ia, old, __float_as_int(val));
        if (prev == old) break;
        old = prev;
    }
}

__device__ __forceinline__ void red_add_v4(float* addr, float4 v) {
    asm volatile("red.global.add.v4.f32 [%0], {%1,%2,%3,%4};"
                 :: "l"(addr), "f"(v.x), "f"(v.y), "f"(v.z), "f"(v.w)
                 : "memory");
}

// ---------------- Edge-index dtype detection + canonicalization ----------------
// If edge_index is int64 (little-endian, values < 50000), every odd 32-bit word
// of the buffer is 0. If int32, odd words are random node ids (P[all 0] ~ 0).
__global__ void detect_kernel(const int* ei) {
    if (threadIdx.x == 0) {
        int is64 = 1;
        for (int i = 0; i < 128; i++) {
            if (ei[2 * i + 1] != 0) { is64 = 0; break; }
        }
        g_is64 = is64;
    }
}

__global__ void canon_kernel(const void* ei) {
    int i = blockIdx.x * blockDim.x + threadIdx.x;
    if (i < NEDGES) {
        if (g_is64) {
            const long long* p = (const long long*)ei;
            g_src[i] = (int)p[i];
            g_dst[i] = (int)p[NEDGES + i];
        } else {
            const int* p = (const int*)ei;
            g_src[i] = p[i];
            g_dst[i] = p[NEDGES + i];
        }
    } else if (i < ETOT) {
        int k = i - NEDGES;   // self loops
        g_src[i] = k;
        g_dst[i] = k;
    }
}

// ---------------- GEMM: Y[N, COLS] = X[N,128] @ W[128, COLS] ----------------
template <int COLS>
__global__ void gemm_kernel(const float* __restrict__ X,
                            const float* __restrict__ W,
                            float* __restrict__ Y) {
    constexpr int TM = 64;
    constexpr int CG = COLS / 4;        // float4 column groups
    constexpr int THREADS = CG * 8;     // 8 row groups
    __shared__ float  Xs[TM][33];
    __shared__ float4 Ws[32][CG];

    const int tid = threadIdx.x;
    const int cg = tid % CG;
    const int rg = tid / CG;            // 0..7
    const int row0 = blockIdx.x * TM;

    float acc[8][4];
#pragma unroll
    for (int r = 0; r < 8; r++)
#pragma unroll
        for (int c = 0; c < 4; c++) acc[r][c] = 0.0f;

    for (int k0 = 0; k0 < 128; k0 += 32) {
        __syncthreads();
        for (int idx = tid; idx < TM * 32; idx += THREADS) {
            int r = idx >> 5, k = idx & 31;
            int gr = row0 + r;
            Xs[r][k] = (gr < NNODES) ? X[gr * 128 + k0 + k] : 0.0f;
        }
        for (int idx = tid; idx < 32 * CG; idx += THREADS) {
            int k = idx / CG, c = idx % CG;
            Ws[k][c] = ((const float4*)W)[(k0 + k) * CG + c];
        }
        __syncthreads();
#pragma unroll
        for (int k = 0; k < 32; k++) {
            float4 w = Ws[k][cg];
#pragma unroll
            for (int r = 0; r < 8; r++) {
                float xv = Xs[rg * 8 + r][k];
                acc[r][0] += xv * w.x;
                acc[r][1] += xv * w.y;
                acc[r][2] += xv * w.z;
                acc[r][3] += xv * w.w;
            }
        }
    }

#pragma unroll
    for (int r = 0; r < 8; r++) {
        int gr = row0 + rg * 8 + r;
        if (gr < NNODES) {
            float4 v = make_float4(acc[r][0], acc[r][1], acc[r][2], acc[r][3]);
            ((float4*)Y)[gr * CG + cg] = v;
        }
    }
}

// ---------------- Per-layer init ----------------
__global__ void init_kernel(int nagg, int nh) {
    int i = blockIdx.x * blockDim.x + threadIdx.x;
    if (i < nagg) g_agg[i] = 0.0f;
    if (i < nh) { g_denom[i] = 0.0f; g_amax[i] = -3.0e38f; }
}

// ---------------- Edge logits + segment max ----------------
// ROWF4 = float4s per node row (32 for 128ch, 16 for 64ch). 32/ROWF4 edges per warp.
template <int ROWF4>
__global__ void edge_logits_kernel(const float* __restrict__ att) {
    constexpr int EPW = 32 / ROWF4;
    constexpr int HEADS = (ROWF4 == 32) ? 2 : 1;
    int gwarp = (blockIdx.x * blockDim.x + threadIdx.x) >> 5;
    int lane = threadIdx.x & 31;
    int sub = lane / ROWF4;
    int l = lane % ROWF4;
    int e = gwarp * EPW + sub;
    if (e >= ETOT) return;

    int s = g_src[e], d = g_dst[e];
    float4 a = ((const float4*)g_xl)[s * ROWF4 + l];
    float4 b = ((const float4*)g_xr)[d * ROWF4 + l];
    float4 w = ((const float4*)att)[l];

    float vx = a.x + b.x, vy = a.y + b.y, vz = a.z + b.z, vw = a.w + b.w;
    vx = vx > 0.f ? vx : 0.2f * vx;
    vy = vy > 0.f ? vy : 0.2f * vy;
    vz = vz > 0.f ? vz : 0.2f * vz;
    vw = vw > 0.f ? vw : 0.2f * vw;
    float p = vx * w.x + vy * w.y + vz * w.z + vw * w.w;

    // reduce within 16 lanes (one head each for ROWF4=32; one edge for ROWF4=16)
    p += __shfl_xor_sync(0xffffffffu, p, 8);
    p += __shfl_xor_sync(0xffffffffu, p, 4);
    p += __shfl_xor_sync(0xffffffffu, p, 2);
    p += __shfl_xor_sync(0xffffffffu, p, 1);

    if ((l & 15) == 0) {
        int h = (ROWF4 == 32) ? (l >> 4) : 0;
        g_ex[e * HEADS + h] = p;
        atomicMaxF(&g_amax[d * HEADS + h], p);
    }
}

// ---------------- exp(logit - max) + segment sum ----------------
template <int HEADS>
__global__ void edge_exp_kernel() {
    int idx = blockIdx.x * blockDim.x + threadIdx.x;
    if (idx >= ETOT * HEADS) return;
    int e = idx / HEADS, h = idx % HEADS;
    int d = g_dst[e];
    float ex = __expf(g_ex[idx] - g_amax[d * HEADS + h]);
    g_ex[idx] = ex;
    atomicAdd(&g_denom[d * HEADS + h], ex);
}

// ---------------- weighted aggregation (scatter-add) ----------------
template <int ROWF4>
__global__ void edge_aggr_kernel() {
    constexpr int EPW = 32 / ROWF4;
    constexpr int HEADS = (ROWF4 == 32) ? 2 : 1;
    int gwarp = (blockIdx.x * blockDim.x + threadIdx.x) >> 5;
    int lane = threadIdx.x & 31;
    int sub = lane / ROWF4;
    int l = lane % ROWF4;
    int e = gwarp * EPW + sub;
    if (e >= ETOT) return;

    int s = g_src[e], d = g_dst[e];
    int h = (ROWF4 == 32) ? (l >> 4) : 0;
    float alpha = g_ex[e * HEADS + h] / g_denom[d * HEADS + h];
    float4 v = ((const float4*)g_xl)[s * ROWF4 + l];
    v.x *= alpha; v.y *= alpha; v.z *= alpha; v.w *= alpha;
    red_add_v4(&g_agg[(d * ROWF4 + l) * 4], v);
}

// ---------------- bias + ELU ----------------
__global__ void finalize_kernel(const float* __restrict__ bias,
                                float* __restrict__ out, int cols) {
    int idx = blockIdx.x * blockDim.x + threadIdx.x;
    if (idx >= NNODES * cols) return;
    int c = idx % cols;
    float v = g_agg[idx] + bias[c];
    out[idx] = v > 0.f ? v : (__expf(v) - 1.0f);
}

// ---------------- Layer driver ----------------
template <int COLS>
static void run_layer(const float* in, const float* Wl, const float* Wr,
                      const float* att, const float* bias, float* out,
                      float* d_xl, float* d_xr) {
    constexpr int HEADS = COLS / 64;
    constexpr int ROWF4 = COLS / 4;
    constexpr int GT = (COLS / 4) * 8;
    constexpr int EPW = 32 / ROWF4;

    gemm_kernel<COLS><<<(NNODES + 63) / 64, GT>>>(in, Wl, d_xl);
    gemm_kernel<COLS><<<(NNODES + 63) / 64, GT>>>(in, Wr, d_xr);
    init_kernel<<<(NNODES * COLS + 255) / 256, 256>>>(NNODES * COLS, NNODES * HEADS);

    int lblocks = (ETOT + 8 * EPW - 1) / (8 * EPW);
    edge_logits_kernel<ROWF4><<<lblocks, 256>>>(att);
    edge_exp_kernel<HEADS><<<(ETOT * HEADS + 255) / 256, 256>>>();
    edge_aggr_kernel<ROWF4><<<lblocks, 256>>>();
    finalize_kernel<<<(NNODES * COLS + 255) / 256, 256>>>(bias, out, COLS);
}

// ---------------- Entry point ----------------
extern "C" void kernel_launch(void* const* d_in, const int* in_sizes, int n_in,
                              void* d_out, int out_size) {
    const float* x    = (const float*)d_in[0];
    const void*  ei   = d_in[1];
    const float* W1l  = (const float*)d_in[2];
    const float* W1r  = (const float*)d_in[3];
    const float* att1 = (const float*)d_in[4];
    const float* b1   = (const float*)d_in[5];
    const float* W2l  = (const float*)d_in[6];
    const float* W2r  = (const float*)d_in[7];
    const float* att2 = (const float*)d_in[8];
    const float* b2   = (const float*)d_in[9];
    const float* W3l  = (const float*)d_in[10];
    const float* W3r  = (const float*)d_in[11];
    const float* att3 = (const float*)d_in[12];
    const float* b3   = (const float*)d_in[13];
    float* out = (float*)d_out;

    float *d_xl, *d_xr, *d_h;
    cudaGetSymbolAddress((void**)&d_xl, g_xl);
    cudaGetSymbolAddress((void**)&d_xr, g_xr);
    cudaGetSymbolAddress((void**)&d_h,  g_h);

    detect_kernel<<<1, 32>>>((const int*)ei);
    canon_kernel<<<(ETOT + 255) / 256, 256>>>(ei);

    run_layer<128>(x,   W1l, W1r, att1, b1, d_h, d_xl, d_xr);
    run_layer<128>(d_h, W2l, W2r, att2, b2, d_h, d_xl, d_xr);
    run_layer<64>(d_h,  W3l, W3r, att3, b3, out, d_xl, d_xr);
}

// round 2
// speedup vs baseline: 1.5163x; 1.5163x over previous
#include <cuda_runtime.h>
#include <cuda_bf16.h>

// ---------------- Problem constants ----------------
#define NNODES 50000
#define NEDGES 800000
#define ETOT   (NEDGES + NNODES)   // + self loops

// ---------------- Device scratch (no allocs allowed) ----------------
__device__ float g_xl[NNODES * 128];
__device__ float g_xr[NNODES * 128];
__device__ float g_h[NNODES * 128];     // layer activation ping buffer
__device__ float g_agg[NNODES * 128];   // unnormalized aggregation target
__device__ float g_denom[NNODES * 2];   // softmax denominators
__device__ int   g_src[ETOT];
__device__ int   g_dst[ETOT];
__device__ int   g_is64;

// ---------------- Helpers ----------------
__device__ __forceinline__ void red_add_v4(float* addr, float4 v) {
    asm volatile("red.global.add.v4.f32 [%0], {%1,%2,%3,%4};"
                 :: "l"(addr), "f"(v.x), "f"(v.y), "f"(v.z), "f"(v.w)
                 : "memory");
}

__device__ __forceinline__ void red_add_f(float* addr, float v) {
    asm volatile("red.global.add.f32 [%0], %1;"
                 :: "l"(addr), "f"(v) : "memory");
}

// ---------------- Edge-index dtype detection + canonicalization ----------------
__global__ void detect_kernel(const int* ei) {
    if (threadIdx.x == 0) {
        int is64 = 1;
        for (int i = 0; i < 128; i++) {
            if (ei[2 * i + 1] != 0) { is64 = 0; break; }
        }
        g_is64 = is64;
    }
}

__global__ void canon_kernel(const void* ei) {
    int i = blockIdx.x * blockDim.x + threadIdx.x;
    if (i < NEDGES) {
        if (g_is64) {
            const long long* p = (const long long*)ei;
            g_src[i] = (int)p[i];
            g_dst[i] = (int)p[NEDGES + i];
        } else {
            const int* p = (const int*)ei;
            g_src[i] = p[i];
            g_dst[i] = p[NEDGES + i];
        }
    } else if (i < ETOT) {
        int k = i - NEDGES;   // self loops
        g_src[i] = k;
        g_dst[i] = k;
    }
}

// ---------------- GEMM: Y[N, COLS] = X[N,128] @ W[128, COLS] ----------------
template <int COLS>
__global__ void gemm_kernel(const float* __restrict__ X,
                            const float* __restrict__ W,
                            float* __restrict__ Y) {
    constexpr int TM = 64;
    constexpr int CG = COLS / 4;        // float4 column groups
    constexpr int THREADS = CG * 8;     // 8 row groups
    __shared__ float  Xs[TM][33];
    __shared__ float4 Ws[32][CG];

    const int tid = threadIdx.x;
    const int cg = tid % CG;
    const int rg = tid / CG;            // 0..7
    const int row0 = blockIdx.x * TM;

    float acc[8][4];
#pragma unroll
    for (int r = 0; r < 8; r++)
#pragma unroll
        for (int c = 0; c < 4; c++) acc[r][c] = 0.0f;

    for (int k0 = 0; k0 < 128; k0 += 32) {
        __syncthreads();
        for (int idx = tid; idx < TM * 32; idx += THREADS) {
            int r = idx >> 5, k = idx & 31;
            int gr = row0 + r;
            Xs[r][k] = (gr < NNODES) ? X[gr * 128 + k0 + k] : 0.0f;
        }
        for (int idx = tid; idx < 32 * CG; idx += THREADS) {
            int k = idx / CG, c = idx % CG;
            Ws[k][c] = ((const float4*)W)[(k0 + k) * CG + c];
        }
        __syncthreads();
#pragma unroll
        for (int k = 0; k < 32; k++) {
            float4 w = Ws[k][cg];
#pragma unroll
            for (int r = 0; r < 8; r++) {
                float xv = Xs[rg * 8 + r][k];
                acc[r][0] += xv * w.x;
                acc[r][1] += xv * w.y;
                acc[r][2] += xv * w.z;
                acc[r][3] += xv * w.w;
            }
        }
    }

#pragma unroll
    for (int r = 0; r < 8; r++) {
        int gr = row0 + rg * 8 + r;
        if (gr < NNODES) {
            float4 v = make_float4(acc[r][0], acc[r][1], acc[r][2], acc[r][3]);
            ((float4*)Y)[gr * CG + cg] = v;
        }
    }
}

// ---------------- Per-layer init ----------------
__global__ void init_kernel(int nagg, int nh) {
    int i = blockIdx.x * blockDim.x + threadIdx.x;
    if (i < nagg) g_agg[i] = 0.0f;
    if (i < nh) g_denom[i] = 0.0f;
}

// ---------------- Fully fused edge pass ----------------
// For each edge: logit = att . LeakyReLU(xl[src] + xr[dst]) per head,
// ex = exp(logit); red-add ex into denom[dst,h]; red-add ex*xl[src] into agg[dst].
// Normalization by denom happens in finalize (mathematically identical to
// per-edge softmax weights; max-shift cancels in the ratio).
// ROWF4 = float4s per node row (32 for 128ch/2 heads, 16 for 64ch/1 head).
template <int ROWF4>
__global__ void edge_fused_kernel(const float* __restrict__ att) {
    constexpr int EPW = 32 / ROWF4;                 // edges per warp
    constexpr int HEADS = (ROWF4 == 32) ? 2 : 1;
    int gwarp = (blockIdx.x * blockDim.x + threadIdx.x) >> 5;
    int lane = threadIdx.x & 31;
    int sub = lane / ROWF4;
    int l = lane % ROWF4;
    int e = gwarp * EPW + sub;
    if (e >= ETOT) return;

    int s = g_src[e], d = g_dst[e];
    float4 a = ((const float4*)g_xl)[s * ROWF4 + l];
    float4 b = ((const float4*)g_xr)[d * ROWF4 + l];
    float4 w = ((const float4*)att)[l];

    float vx = a.x + b.x, vy = a.y + b.y, vz = a.z + b.z, vw = a.w + b.w;
    vx = vx > 0.f ? vx : 0.2f * vx;
    vy = vy > 0.f ? vy : 0.2f * vy;
    vz = vz > 0.f ? vz : 0.2f * vz;
    vw = vw > 0.f ? vw : 0.2f * vw;
    float p = vx * w.x + vy * w.y + vz * w.z + vw * w.w;

    // reduce within each aligned 16-lane group (one head / one edge-half)
    p += __shfl_xor_sync(0xffffffffu, p, 8);
    p += __shfl_xor_sync(0xffffffffu, p, 4);
    p += __shfl_xor_sync(0xffffffffu, p, 2);
    p += __shfl_xor_sync(0xffffffffu, p, 1);

    float ex = __expf(p);   // all 16 lanes of the group hold the same value

    // weighted message: ex * xl[src] chunk (already in registers)
    float4 v = make_float4(a.x * ex, a.y * ex, a.z * ex, a.w * ex);
    red_add_v4(&g_agg[(d * ROWF4 + l) * 4], v);

    if ((l & 15) == 0) {
        int h = (ROWF4 == 32) ? (l >> 4) : 0;
        red_add_f(&g_denom[d * HEADS + h], ex);
    }
}

// ---------------- normalize + bias + ELU ----------------
template <int COLS>
__global__ void finalize_kernel(const float* __restrict__ bias,
                                float* __restrict__ out) {
    constexpr int HEADS = COLS / 64;
    int idx = blockIdx.x * blockDim.x + threadIdx.x;
    if (idx >= NNODES * COLS) return;
    int c = idx % COLS;
    int node = idx / COLS;
    int h = (HEADS == 2) ? (c >> 6) : 0;
    float v = g_agg[idx] / g_denom[node * HEADS + h] + bias[c];
    out[idx] = v > 0.f ? v : (__expf(v) - 1.0f);
}

// ---------------- Layer driver ----------------
template <int COLS>
static void run_layer(const float* in, const float* Wl, const float* Wr,
                      const float* att, const float* bias, float* out,
                      float* d_xl, float* d_xr) {
    constexpr int HEADS = COLS / 64;
    constexpr int ROWF4 = COLS / 4;
    constexpr int GT = (COLS / 4) * 8;
    constexpr int EPW = 32 / ROWF4;

    gemm_kernel<COLS><<<(NNODES + 63) / 64, GT>>>(in, Wl, d_xl);
    gemm_kernel<COLS><<<(NNODES + 63) / 64, GT>>>(in, Wr, d_xr);
    init_kernel<<<(NNODES * COLS + 255) / 256, 256>>>(NNODES * COLS, NNODES * HEADS);

    int lblocks = (ETOT + 8 * EPW - 1) / (8 * EPW);
    edge_fused_kernel<ROWF4><<<lblocks, 256>>>(att);
    finalize_kernel<COLS><<<(NNODES * COLS + 255) / 256, 256>>>(bias, out);
}

// ---------------- Entry point ----------------
extern "C" void kernel_launch(void* const* d_in, const int* in_sizes, int n_in,
                              void* d_out, int out_size) {
    const float* x    = (const float*)d_in[0];
    const void*  ei   = d_in[1];
    const float* W1l  = (const float*)d_in[2];
    const float* W1r  = (const float*)d_in[3];
    const float* att1 = (const float*)d_in[4];
    const float* b1   = (const float*)d_in[5];
    const float* W2l  = (const float*)d_in[6];
    const float* W2r  = (const float*)d_in[7];
    const float* att2 = (const float*)d_in[8];
    const float* b2   = (const float*)d_in[9];
    const float* W3l  = (const float*)d_in[10];
    const float* W3r  = (const float*)d_in[11];
    const float* att3 = (const float*)d_in[12];
    const float* b3   = (const float*)d_in[13];
    float* out = (float*)d_out;

    float *d_xl, *d_xr, *d_h;
    cudaGetSymbolAddress((void**)&d_xl, g_xl);
    cudaGetSymbolAddress((void**)&d_xr, g_xr);
    cudaGetSymbolAddress((void**)&d_h,  g_h);

    detect_kernel<<<1, 32>>>((const int*)ei);
    canon_kernel<<<(ETOT + 255) / 256, 256>>>(ei);

    run_layer<128>(x,   W1l, W1r, att1, b1, d_h, d_xl, d_xr);
    run_layer<128>(d_h, W2l, W2r, att2, b2, d_h, d_xl, d_xr);
    run_layer<64>(d_h,  W3l, W3r, att3, b3, out, d_xl, d_xr);
}

// round 3
// speedup vs baseline: 2.1128x; 1.3934x over previous
#include <cuda_runtime.h>
#include <cuda_bf16.h>

// ---------------- Problem constants ----------------
#define NNODES 50000
#define NEDGES 800000
#define ETOT   (NEDGES + NNODES)   // + self loops

// ---------------- Device scratch (no allocs allowed) ----------------
__device__ float g_xl[NNODES * 128];
__device__ float g_xr[NNODES * 128];
__device__ float g_h[NNODES * 128];      // layer activation ping buffer
__device__ int   g_src[ETOT];
__device__ int   g_dst[ETOT];
__device__ int   g_csrc[ETOT];           // src ids sorted by dst (CSR)
__device__ int   g_rowptr[NNODES + 1];
__device__ int   g_deg[NNODES];
__device__ int   g_cnt[NNODES];
__device__ int   g_is64;

// ---------------- Edge-index dtype detection ----------------
__global__ void detect_kernel(const int* ei) {
    if (threadIdx.x == 0) {
        int is64 = 1;
        for (int i = 0; i < 128; i++) {
            if (ei[2 * i + 1] != 0) { is64 = 0; break; }
        }
        g_is64 = is64;
    }
}

__global__ void zero_counts_kernel() {
    int i = blockIdx.x * blockDim.x + threadIdx.x;
    if (i < NNODES) { g_deg[i] = 0; g_cnt[i] = 0; }
}

// canonicalize edges (either dtype), append self loops, histogram degrees
__global__ void canon_hist_kernel(const void* ei) {
    int i = blockIdx.x * blockDim.x + threadIdx.x;
    if (i >= ETOT) return;
    int s, d;
    if (i < NEDGES) {
        if (g_is64) {
            const long long* p = (const long long*)ei;
            s = (int)p[i];
            d = (int)p[NEDGES + i];
        } else {
            const int* p = (const int*)ei;
            s = p[i];
            d = p[NEDGES + i];
        }
    } else {
        s = d = i - NEDGES;   // self loop
    }
    g_src[i] = s;
    g_dst[i] = d;
    atomicAdd(&g_deg[d], 1);
}

// single-block exclusive scan of g_deg -> g_rowptr (warp-shuffle based)
__global__ void scan_kernel() {
    __shared__ int warp_tot[32];
    __shared__ int s_carry;
    const int t = threadIdx.x;          // 1024 threads
    const int lane = t & 31, wid = t >> 5;
    if (t == 0) s_carry = 0;
    __syncthreads();

    for (int base = 0; base < NNODES; base += 1024) {
        int v = (base + t < NNODES) ? g_deg[base + t] : 0;
        // warp inclusive scan
        int incl = v;
#pragma unroll
        for (int off = 1; off < 32; off <<= 1) {
            int x = __shfl_up_sync(0xffffffffu, incl, off);
            if (lane >= off) incl += x;
        }
        if (lane == 31) warp_tot[wid] = incl;
        __syncthreads();
        if (wid == 0) {
            int wv = warp_tot[lane];
            int wi = wv;
#pragma unroll
            for (int off = 1; off < 32; off <<= 1) {
                int x = __shfl_up_sync(0xffffffffu, wi, off);
                if (lane >= off) wi += x;
            }
            warp_tot[lane] = wi - wv;   // exclusive warp offsets
        }
        __syncthreads();
        int excl = s_carry + warp_tot[wid] + incl - v;
        if (base + t < NNODES) g_rowptr[base + t] = excl;
        __syncthreads();
        if (t == 1023) s_carry = excl + v;
        __syncthreads();
    }
    if (t == 0) g_rowptr[NNODES] = s_carry;
}

__global__ void scatter_kernel() {
    int i = blockIdx.x * blockDim.x + threadIdx.x;
    if (i >= ETOT) return;
    int d = g_dst[i];
    int pos = g_rowptr[d] + atomicAdd(&g_cnt[d], 1);
    g_csrc[pos] = g_src[i];
}

// ---------------- Dual GEMM: Yl = X@Wl, Yr = X@Wr  (X: [N,128]) ----------------
template <int COLS>
__global__ void gemm_dual_kernel(const float* __restrict__ X,
                                 const float* __restrict__ Wl,
                                 const float* __restrict__ Wr,
                                 float* __restrict__ Yl,
                                 float* __restrict__ Yr) {
    constexpr int TM = 64;
    constexpr int CG = COLS / 4;          // float4 column groups
    constexpr int RG = 256 / CG;          // row groups
    constexpr int RPT = TM / RG;          // rows per thread (8 or 4)
    constexpr int RF4 = RPT / 4;          // float4 X chunks per thread (2 or 1)

    __shared__ float  Xs[32][68];         // transposed: [k][row], 16B-aligned rows
    __shared__ float4 Wsl[32][CG];
    __shared__ float4 Wsr[32][CG];

    const int tid = threadIdx.x;
    const int cg = tid % CG;
    const int rg = tid / CG;
    const int row0 = blockIdx.x * TM;

    float4 accl[RPT], accr[RPT];
#pragma unroll
    for (int r = 0; r < RPT; r++) {
        accl[r] = make_float4(0.f, 0.f, 0.f, 0.f);
        accr[r] = make_float4(0.f, 0.f, 0.f, 0.f);
    }

    for (int k0 = 0; k0 < 128; k0 += 32) {
        __syncthreads();
        // load X tile transposed: Xs[k][r] = X[row0+r][k0+k]
#pragma unroll
        for (int u = tid; u < TM * 8; u += 256) {
            int r = u & 63, k4 = u >> 6;          // k4: 0..7
            float4 xv = make_float4(0.f, 0.f, 0.f, 0.f);
            int gr = row0 + r;
            if (gr < NNODES)
                xv = *(const float4*)&X[gr * 128 + k0 + k4 * 4];
            Xs[k4 * 4 + 0][r] = xv.x;
            Xs[k4 * 4 + 1][r] = xv.y;
            Xs[k4 * 4 + 2][r] = xv.z;
            Xs[k4 * 4 + 3][r] = xv.w;
        }
#pragma unroll
        for (int u = tid; u < 32 * CG; u += 256) {
            int k = u / CG, c = u % CG;
            Wsl[k][c] = ((const float4*)Wl)[(k0 + k) * CG + c];
            Wsr[k][c] = ((const float4*)Wr)[(k0 + k) * CG + c];
        }
        __syncthreads();

#pragma unroll 8
        for (int k = 0; k < 32; k++) {
            float4 wl = Wsl[k][cg];
            float4 wr = Wsr[k][cg];
            const float4* xrow = (const float4*)&Xs[k][0];
#pragma unroll
            for (int q = 0; q < RF4; q++) {
                float4 xv = xrow[rg * RF4 + q];
#pragma unroll
                for (int j = 0; j < 4; j++) {
                    float x = (j == 0) ? xv.x : (j == 1) ? xv.y : (j == 2) ? xv.z : xv.w;
                    int r = q * 4 + j;
                    accl[r].x += x * wl.x; accl[r].y += x * wl.y;
                    accl[r].z += x * wl.z; accl[r].w += x * wl.w;
                    accr[r].x += x * wr.x; accr[r].y += x * wr.y;
                    accr[r].z += x * wr.z; accr[r].w += x * wr.w;
                }
            }
        }
    }

#pragma unroll
    for (int r = 0; r < RPT; r++) {
        int gr = row0 + rg * RPT + r;
        if (gr < NNODES) {
            ((float4*)Yl)[gr * CG + cg] = accl[r];
            ((float4*)Yr)[gr * CG + cg] = accr[r];
        }
    }
}

// ---------------- CSR edge pass: warp (or half-warp) per destination node ----
// Computes out[d] = ELU( (sum_e exp(l_e) * xl[src_e]) / (sum_e exp(l_e)) + bias )
// ROWF4=32 -> 128 ch / 2 heads, full warp per node.
// ROWF4=16 -> 64 ch / 1 head, half warp per node (2 nodes per warp).
template <int ROWF4>
__global__ void csr_edge_kernel(const float* __restrict__ att,
                                const float* __restrict__ bias,
                                float* __restrict__ out) {
    constexpr int NPW = 32 / ROWF4;       // nodes per warp
    int gwarp = (blockIdx.x * blockDim.x + threadIdx.x) >> 5;
    int lane = threadIdx.x & 31;
    int sub = lane / ROWF4;               // which node within warp
    int l = lane % ROWF4;
    int d = gwarp * NPW + sub;
    if (d >= NNODES) return;

    float4 b = ((const float4*)g_xr)[d * ROWF4 + l];
    float4 w = ((const float4*)att)[l];

    float4 acc = make_float4(0.f, 0.f, 0.f, 0.f);
    float den = 0.f;

    int i = g_rowptr[d];
    const int end = g_rowptr[d + 1];

    int s = g_csrc[i];
    float4 a = ((const float4*)g_xl)[s * ROWF4 + l];

    for (; i < end; ) {
        int j = i + 1;
        int s2 = 0;
        float4 a2 = make_float4(0.f, 0.f, 0.f, 0.f);
        if (j < end) {
            s2 = g_csrc[j];
            a2 = ((const float4*)g_xl)[s2 * ROWF4 + l];
        }

        float vx = a.x + b.x, vy = a.y + b.y, vz = a.z + b.z, vw = a.w + b.w;
        vx = vx > 0.f ? vx : 0.2f * vx;
        vy = vy > 0.f ? vy : 0.2f * vy;
        vz = vz > 0.f ? vz : 0.2f * vz;
        vw = vw > 0.f ? vw : 0.2f * vw;
        float p = vx * w.x + vy * w.y + vz * w.z + vw * w.w;

        // reduce within aligned 16-lane group (per head / per node-half)
        p += __shfl_xor_sync(0xffffffffu, p, 8);
        p += __shfl_xor_sync(0xffffffffu, p, 4);
        p += __shfl_xor_sync(0xffffffffu, p, 2);
        p += __shfl_xor_sync(0xffffffffu, p, 1);

        float ex = __expf(p);
        acc.x += ex * a.x; acc.y += ex * a.y;
        acc.z += ex * a.z; acc.w += ex * a.w;
        den += ex;

        a = a2;
        i = j;
    }

    float4 bi = ((const float4*)bias)[l];
    float inv = 1.0f / den;
    float4 o;
    o.x = acc.x * inv + bi.x;
    o.y = acc.y * inv + bi.y;
    o.z = acc.z * inv + bi.z;
    o.w = acc.w * inv + bi.w;
    o.x = o.x > 0.f ? o.x : (__expf(o.x) - 1.f);
    o.y = o.y > 0.f ? o.y : (__expf(o.y) - 1.f);
    o.z = o.z > 0.f ? o.z : (__expf(o.z) - 1.f);
    o.w = o.w > 0.f ? o.w : (__expf(o.w) - 1.f);
    ((float4*)out)[d * ROWF4 + l] = o;
}

// ---------------- Layer driver ----------------
template <int COLS>
static void run_layer(const float* in, const float* Wl, const float* Wr,
                      const float* att, const float* bias, float* out,
                      float* d_xl, float* d_xr) {
    constexpr int ROWF4 = COLS / 4;
    constexpr int NPW = 32 / ROWF4;
    gemm_dual_kernel<COLS><<<(NNODES + 63) / 64, 256>>>(in, Wl, Wr, d_xl, d_xr);
    int nwarps = (NNODES + NPW - 1) / NPW;
    csr_edge_kernel<ROWF4><<<(nwarps * 32 + 255) / 256, 256>>>(att, bias, out);
}

// ---------------- Entry point ----------------
extern "C" void kernel_launch(void* const* d_in, const int* in_sizes, int n_in,
                              void* d_out, int out_size) {
    const float* x    = (const float*)d_in[0];
    const void*  ei   = d_in[1];
    const float* W1l  = (const float*)d_in[2];
    const float* W1r  = (const float*)d_in[3];
    const float* att1 = (const float*)d_in[4];
    const float* b1   = (const float*)d_in[5];
    const float* W2l  = (const float*)d_in[6];
    const float* W2r  = (const float*)d_in[7];
    const float* att2 = (const float*)d_in[8];
    const float* b2   = (const float*)d_in[9];
    const float* W3l  = (const float*)d_in[10];
    const float* W3r  = (const float*)d_in[11];
    const float* att3 = (const float*)d_in[12];
    const float* b3   = (const float*)d_in[13];
    float* out = (float*)d_out;

    float *d_xl, *d_xr, *d_h;
    cudaGetSymbolAddress((void**)&d_xl, g_xl);
    cudaGetSymbolAddress((void**)&d_xr, g_xr);
    cudaGetSymbolAddress((void**)&d_h,  g_h);

    // one-time preprocessing: dtype canon + CSR build (dst-sorted)
    detect_kernel<<<1, 32>>>((const int*)ei);
    zero_counts_kernel<<<(NNODES + 255) / 256, 256>>>();
    canon_hist_kernel<<<(ETOT + 255) / 256, 256>>>(ei);
    scan_kernel<<<1, 1024>>>();
    scatter_kernel<<<(ETOT + 255) / 256, 256>>>();

    run_layer<128>(x,   W1l, W1r, att1, b1, d_h, d_xl, d_xr);
    run_layer<128>(d_h, W2l, W2r, att2, b2, d_h, d_xl, d_xr);
    run_layer<64>(d_h,  W3l, W3r, att3, b3, out, d_xl, d_xr);
}

// round 4
// speedup vs baseline: 2.4825x; 1.1750x over previous
#include <cuda_runtime.h>
#include <cuda_bf16.h>

// ---------------- Problem constants ----------------
#define NNODES 50000
#define NEDGES 800000
#define ETOT   (NEDGES + NNODES)   // + self loops
#define NBLK   ((NNODES + 1023) / 1024)   // 49 scan blocks

// ---------------- Device scratch (no allocs allowed) ----------------
__device__ float g_xl[NNODES * 128];
__device__ float g_xr[NNODES * 128];
__device__ float g_h[NNODES * 128];      // layer activation ping buffer
__device__ int   g_src[ETOT];
__device__ int   g_dst[ETOT];
__device__ int   g_csrc[ETOT];           // src ids sorted by dst (CSR)
__device__ int   g_rowptr[NNODES + 1];
__device__ int   g_deg[NNODES];
__device__ int   g_cnt[NNODES];
__device__ int   g_bsum[NBLK];
__device__ int   g_boff[NBLK];
__device__ int   g_is64;

// ---------------- zero counters + parallel dtype detect ----------------
// int64 edge_index (values < 50000) has all odd 32-bit words zero.
__global__ void prep_kernel(const int* ei) {
    int i = blockIdx.x * blockDim.x + threadIdx.x;
    if (i < NNODES) { g_deg[i] = 0; g_cnt[i] = 0; }
    if (blockIdx.x == 0 && threadIdx.x < 32) {
        int nz = 0;
#pragma unroll
        for (int q = 0; q < 4; q++)
            nz |= ei[2 * (threadIdx.x * 4 + q) + 1];
        unsigned any = __ballot_sync(0xffffffffu, nz != 0);
        if (threadIdx.x == 0) g_is64 = (any == 0u);
    }
}

// canonicalize edges (either dtype), append self loops, histogram degrees
__global__ void canon_hist_kernel(const void* ei) {
    int i = blockIdx.x * blockDim.x + threadIdx.x;
    if (i >= ETOT) return;
    int s, d;
    if (i < NEDGES) {
        if (g_is64) {
            const long long* p = (const long long*)ei;
            s = (int)p[i];
            d = (int)p[NEDGES + i];
        } else {
            const int* p = (const int*)ei;
            s = p[i];
            d = p[NEDGES + i];
        }
    } else {
        s = d = i - NEDGES;   // self loop
    }
    g_src[i] = s;
    g_dst[i] = d;
    atomicAdd(&g_deg[d], 1);
}

// ---------------- Multi-block exclusive scan of g_deg -> g_rowptr ------------
__global__ void scan1_kernel() {
    __shared__ int wtot[32];
    const int t = threadIdx.x, lane = t & 31, wid = t >> 5;
    const int gi = blockIdx.x * 1024 + t;
    int v = (gi < NNODES) ? g_deg[gi] : 0;
    int incl = v;
#pragma unroll
    for (int off = 1; off < 32; off <<= 1) {
        int x = __shfl_up_sync(0xffffffffu, incl, off);
        if (lane >= off) incl += x;
    }
    if (lane == 31) wtot[wid] = incl;
    __syncthreads();
    if (wid == 0) {
        int wv = wtot[lane];
        int wi = wv;
#pragma unroll
        for (int off = 1; off < 32; off <<= 1) {
            int x = __shfl_up_sync(0xffffffffu, wi, off);
            if (lane >= off) wi += x;
        }
        wtot[lane] = wi - wv;     // exclusive warp offsets
    }
    __syncthreads();
    int excl = wtot[wid] + incl - v;
    if (gi < NNODES) g_rowptr[gi] = excl;
    if (t == 1023) g_bsum[blockIdx.x] = excl + v;
}

__global__ void scan2_kernel() {
    if (threadIdx.x == 0) {
        int t = 0;
#pragma unroll
        for (int ib = 0; ib < NBLK; ib++) {
            int v = g_bsum[ib];
            g_boff[ib] = t;
            t += v;
        }
        g_rowptr[NNODES] = t;
    }
}

__global__ void scan3_kernel() {
    int gi = blockIdx.x * 1024 + threadIdx.x;
    if (gi < NNODES && blockIdx.x > 0) g_rowptr[gi] += g_boff[blockIdx.x];
}

__global__ void scatter_kernel() {
    int i = blockIdx.x * blockDim.x + threadIdx.x;
    if (i >= ETOT) return;
    int d = g_dst[i];
    int pos = g_rowptr[d] + atomicAdd(&g_cnt[d], 1);
    g_csrc[pos] = g_src[i];
}

// ---------------- Dual GEMM: Yl = X@Wl, Yr = X@Wr  (X: [N,128]) ----------------
template <int COLS>
__global__ void gemm_dual_kernel(const float* __restrict__ X,
                                 const float* __restrict__ Wl,
                                 const float* __restrict__ Wr,
                                 float* __restrict__ Yl,
                                 float* __restrict__ Yr) {
    constexpr int TM = 64;
    constexpr int CG = COLS / 4;          // float4 column groups
    constexpr int RG = 256 / CG;          // row groups
    constexpr int RPT = TM / RG;          // rows per thread (8 or 4)
    constexpr int RF4 = RPT / 4;          // float4 X chunks per thread (2 or 1)

    __shared__ float  Xs[32][68];         // transposed: [k][row]
    __shared__ float4 Wsl[32][CG];
    __shared__ float4 Wsr[32][CG];

    const int tid = threadIdx.x;
    const int cg = tid % CG;
    const int rg = tid / CG;
    const int row0 = blockIdx.x * TM;

    float4 accl[RPT], accr[RPT];
#pragma unroll
    for (int r = 0; r < RPT; r++) {
        accl[r] = make_float4(0.f, 0.f, 0.f, 0.f);
        accr[r] = make_float4(0.f, 0.f, 0.f, 0.f);
    }

    for (int k0 = 0; k0 < 128; k0 += 32) {
        __syncthreads();
#pragma unroll
        for (int u = tid; u < TM * 8; u += 256) {
            int r = u & 63, k4 = u >> 6;
            float4 xv = make_float4(0.f, 0.f, 0.f, 0.f);
            int gr = row0 + r;
            if (gr < NNODES)
                xv = *(const float4*)&X[gr * 128 + k0 + k4 * 4];
            Xs[k4 * 4 + 0][r] = xv.x;
            Xs[k4 * 4 + 1][r] = xv.y;
            Xs[k4 * 4 + 2][r] = xv.z;
            Xs[k4 * 4 + 3][r] = xv.w;
        }
#pragma unroll
        for (int u = tid; u < 32 * CG; u += 256) {
            int k = u / CG, c = u % CG;
            Wsl[k][c] = ((const float4*)Wl)[(k0 + k) * CG + c];
            Wsr[k][c] = ((const float4*)Wr)[(k0 + k) * CG + c];
        }
        __syncthreads();

#pragma unroll 8
        for (int k = 0; k < 32; k++) {
            float4 wl = Wsl[k][cg];
            float4 wr = Wsr[k][cg];
            const float4* xrow = (const float4*)&Xs[k][0];
#pragma unroll
            for (int q = 0; q < RF4; q++) {
                float4 xv = xrow[rg * RF4 + q];
#pragma unroll
                for (int j = 0; j < 4; j++) {
                    float x = (j == 0) ? xv.x : (j == 1) ? xv.y : (j == 2) ? xv.z : xv.w;
                    int r = q * 4 + j;
                    accl[r].x += x * wl.x; accl[r].y += x * wl.y;
                    accl[r].z += x * wl.z; accl[r].w += x * wl.w;
                    accr[r].x += x * wr.x; accr[r].y += x * wr.y;
                    accr[r].z += x * wr.z; accr[r].w += x * wr.w;
                }
            }
        }
    }

#pragma unroll
    for (int r = 0; r < RPT; r++) {
        int gr = row0 + rg * RPT + r;
        if (gr < NNODES) {
            ((float4*)Yl)[gr * CG + cg] = accl[r];
            ((float4*)Yr)[gr * CG + cg] = accr[r];
        }
    }
}

// ---------------- CSR edge pass: 2-edge software-pipelined ----------------
// out[d] = ELU( (sum_e exp(l_e) * xl[src_e]) / (sum_e exp(l_e)) + bias )
template <int ROWF4>
__global__ void csr_edge_kernel(const float* __restrict__ att,
                                const float* __restrict__ bias,
                                float* __restrict__ out) {
    constexpr int NPW = 32 / ROWF4;       // nodes per warp
    int gwarp = (blockIdx.x * blockDim.x + threadIdx.x) >> 5;
    int lane = threadIdx.x & 31;
    int sub = lane / ROWF4;
    int l = lane % ROWF4;
    int d = gwarp * NPW + sub;
    if (d >= NNODES) return;

    const float4* xl4 = (const float4*)g_xl;
    float4 b = ((const float4*)g_xr)[d * ROWF4 + l];
    float4 w = ((const float4*)att)[l];

    float4 acc = make_float4(0.f, 0.f, 0.f, 0.f);
    float den = 0.f;

    int i = g_rowptr[d];
    const int end = g_rowptr[d + 1];

    // load first pair (every node has >=1 edge: self loop)
    int s0 = g_csrc[i];
    int s1 = (i + 1 < end) ? g_csrc[i + 1] : 0;
    float4 a0 = xl4[s0 * ROWF4 + l];
    float4 a1 = xl4[s1 * ROWF4 + l];

    while (i < end) {
        const int ni = i + 2;
        // prefetch next pair (speculative index 0 when past end)
        int t0 = (ni < end) ? g_csrc[ni] : 0;
        int t1 = (ni + 1 < end) ? g_csrc[ni + 1] : 0;
        float4 n0 = xl4[t0 * ROWF4 + l];
        float4 n1 = xl4[t1 * ROWF4 + l];

        // logits for both edges (independent chains)
        float vx0 = a0.x + b.x, vy0 = a0.y + b.y, vz0 = a0.z + b.z, vw0 = a0.w + b.w;
        float vx1 = a1.x + b.x, vy1 = a1.y + b.y, vz1 = a1.z + b.z, vw1 = a1.w + b.w;
        vx0 = vx0 > 0.f ? vx0 : 0.2f * vx0;  vx1 = vx1 > 0.f ? vx1 : 0.2f * vx1;
        vy0 = vy0 > 0.f ? vy0 : 0.2f * vy0;  vy1 = vy1 > 0.f ? vy1 : 0.2f * vy1;
        vz0 = vz0 > 0.f ? vz0 : 0.2f * vz0;  vz1 = vz1 > 0.f ? vz1 : 0.2f * vz1;
        vw0 = vw0 > 0.f ? vw0 : 0.2f * vw0;  vw1 = vw1 > 0.f ? vw1 : 0.2f * vw1;
        float p0 = vx0 * w.x + vy0 * w.y + vz0 * w.z + vw0 * w.w;
        float p1 = vx1 * w.x + vy1 * w.y + vz1 * w.z + vw1 * w.w;

        // interleaved 16-lane-group reductions
        p0 += __shfl_xor_sync(0xffffffffu, p0, 8);
        p1 += __shfl_xor_sync(0xffffffffu, p1, 8);
        p0 += __shfl_xor_sync(0xffffffffu, p0, 4);
        p1 += __shfl_xor_sync(0xffffffffu, p1, 4);
        p0 += __shfl_xor_sync(0xffffffffu, p0, 2);
        p1 += __shfl_xor_sync(0xffffffffu, p1, 2);
        p0 += __shfl_xor_sync(0xffffffffu, p0, 1);
        p1 += __shfl_xor_sync(0xffffffffu, p1, 1);

        float ex0 = __expf(p0);
        float ex1 = (i + 1 < end) ? __expf(p1) : 0.f;

        acc.x += ex0 * a0.x + ex1 * a1.x;
        acc.y += ex0 * a0.y + ex1 * a1.y;
        acc.z += ex0 * a0.z + ex1 * a1.z;
        acc.w += ex0 * a0.w + ex1 * a1.w;
        den += ex0 + ex1;

        a0 = n0; a1 = n1;
        i = ni;
    }

    float4 bi = ((const float4*)bias)[l];
    float inv = 1.0f / den;
    float4 o;
    o.x = acc.x * inv + bi.x;
    o.y = acc.y * inv + bi.y;
    o.z = acc.z * inv + bi.z;
    o.w = acc.w * inv + bi.w;
    o.x = o.x > 0.f ? o.x : (__expf(o.x) - 1.f);
    o.y = o.y > 0.f ? o.y : (__expf(o.y) - 1.f);
    o.z = o.z > 0.f ? o.z : (__expf(o.z) - 1.f);
    o.w = o.w > 0.f ? o.w : (__expf(o.w) - 1.f);
    ((float4*)out)[d * ROWF4 + l] = o;
}

// ---------------- Layer driver ----------------
template <int COLS>
static void run_layer(const float* in, const float* Wl, const float* Wr,
                      const float* att, const float* bias, float* out,
                      float* d_xl, float* d_xr) {
    constexpr int ROWF4 = COLS / 4;
    constexpr int NPW = 32 / ROWF4;
    gemm_dual_kernel<COLS><<<(NNODES + 63) / 64, 256>>>(in, Wl, Wr, d_xl, d_xr);
    int nwarps = (NNODES + NPW - 1) / NPW;
    csr_edge_kernel<ROWF4><<<(nwarps * 32 + 255) / 256, 256>>>(att, bias, out);
}

// ---------------- Entry point ----------------
extern "C" void kernel_launch(void* const* d_in, const int* in_sizes, int n_in,
                              void* d_out, int out_size) {
    const float* x    = (const float*)d_in[0];
    const void*  ei   = d_in[1];
    const float* W1l  = (const float*)d_in[2];
    const float* W1r  = (const float*)d_in[3];
    const float* att1 = (const float*)d_in[4];
    const float* b1   = (const float*)d_in[5];
    const float* W2l  = (const float*)d_in[6];
    const float* W2r  = (const float*)d_in[7];
    const float* att2 = (const float*)d_in[8];
    const float* b2   = (const float*)d_in[9];
    const float* W3l  = (const float*)d_in[10];
    const float* W3r  = (const float*)d_in[11];
    const float* att3 = (const float*)d_in[12];
    const float* b3   = (const float*)d_in[13];
    float* out = (float*)d_out;

    float *d_xl, *d_xr, *d_h;
    cudaGetSymbolAddress((void**)&d_xl, g_xl);
    cudaGetSymbolAddress((void**)&d_xr, g_xr);
    cudaGetSymbolAddress((void**)&d_h,  g_h);

    // one-time preprocessing: dtype canon + CSR build (dst-sorted)
    prep_kernel<<<(NNODES + 255) / 256, 256>>>((const int*)ei);
    canon_hist_kernel<<<(ETOT + 255) / 256, 256>>>(ei);
    scan1_kernel<<<NBLK, 1024>>>();
    scan2_kernel<<<1, 32>>>();
    scan3_kernel<<<NBLK, 1024>>>();
    scatter_kernel<<<(ETOT + 255) / 256, 256>>>();

    run_layer<128>(x,   W1l, W1r, att1, b1, d_h, d_xl, d_xr);
    run_layer<128>(d_h, W2l, W2r, att2, b2, d_h, d_xl, d_xr);
    run_layer<64>(d_h,  W3l, W3r, att3, b3, out, d_xl, d_xr);
}